// round 14
// speedup vs baseline: 4.5454x; 1.0911x over previous
#include <cuda_runtime.h>
#include <cuda_bf16.h>
#include <math.h>
#include <stdint.h>

static constexpr int NMAXN = 8000;
static constexpr int EMAX  = 96000;

// ---- fp32 scratch ----
static constexpr size_t NV_OFF   = 0;                                  // nv:   N x 192
static constexpr size_t R_OFF    = NV_OFF   + (size_t)NMAXN*192;       // R:    E x 9
static constexpr size_t AGGS_OFF = R_OFF    + (size_t)EMAX*9;          // aggs: N x 128
static constexpr size_t AGGV_OFF = AGGS_OFF + (size_t)NMAXN*128;       // aggv: 3 x N x 64
static constexpr size_t TG_OFF   = AGGV_OFF + (size_t)3*NMAXN*64;      // tg:   N x 64
static constexpr size_t TOTAL_F  = TG_OFF   + (size_t)NMAXN*64;
__device__ __align__(256) float g_buf[TOTAL_F];

// ---- bf16 scratch ----
static constexpr size_t NSB   = 0;
static constexpr size_t ESVB  = NSB   + (size_t)NMAXN*128;
static constexpr size_t VF12B = ESVB  + (size_t)EMAX*320;
static constexpr size_t LATB  = VF12B + (size_t)EMAX*384;
static constexpr size_t GSB   = LATB  + (size_t)EMAX*128;
static constexpr size_t GVMB  = GSB   + (size_t)NMAXN*128;
static constexpr size_t AGSB  = GVMB  + (size_t)3*NMAXN*64;
static constexpr size_t AGVB  = AGSB  + (size_t)NMAXN*128;
static constexpr size_t PROJB = AGVB  + (size_t)3*NMAXN*64;            // proj: N x 512
static constexpr size_t GVB   = PROJB + (size_t)NMAXN*512;             // gv:   E x 128
static constexpr size_t WENVB = GVB   + (size_t)EMAX*128;              // wenv: E x 192
static constexpr size_t WCPT  = WENVB + (size_t)EMAX*192;              // 128K x 512N
static constexpr size_t W0MT  = WCPT  + (size_t)128*512;               // 320K x 256N
static constexpr size_t W1CT  = W0MT  + (size_t)320*256;               // 384K x 128N
static constexpr size_t ENVT  = W1CT  + (size_t)384*128;               // 128K x 192N
static constexpr size_t LPWST = ENVT  + (size_t)128*192;               // 128 x 128
static constexpr size_t LPWVT = LPWST + (size_t)128*128;               // 64 x 64
static constexpr size_t WSC   = LPWVT + (size_t)64*64;                 // 128u x 64t x 192
static constexpr size_t WVVT  = WSC   + (size_t)128*64*192;            // 64u x 64t x 64
static constexpr size_t OHLWT = WVVT  + (size_t)64*64*64;              // 128 x 128
static constexpr size_t OHLVT = OHLWT + (size_t)128*128;               // 64 x 64
static constexpr size_t TOTAL_B = OHLVT + (size_t)64*64;
__device__ __align__(256) __nv_bfloat16 g_bbuf[TOTAL_B];

__device__ int g_idx[2*EMAX];
__device__ int g_cnt[128];
__device__ int g_offs[65];
__device__ int g_order[NMAXN];

typedef __nv_bfloat16 bf16;
typedef __nv_bfloat162 bf162;
__device__ __forceinline__ bf162 f2b2(float a, float b) { return __floats2bfloat162_rn(a, b); }

// ---------------------------------------------------------------------------
__global__ void zero_kernel(float* __restrict__ p, size_t n) {
    size_t i = (size_t)blockIdx.x*blockDim.x + threadIdx.x;
    if (i < n) p[i] = 0.f;
}
__global__ void c2b_kernel(const float* __restrict__ in, bf16* __restrict__ out, size_t n) {
    size_t i = (size_t)blockIdx.x*blockDim.x + threadIdx.x;
    if (i < n) out[i] = __float2bfloat16(in[i]);
}
__global__ void count_kernel(const int* __restrict__ at, int* __restrict__ cnt, int N) {
    int n = blockIdx.x*blockDim.x + threadIdx.x;
    if (n < N) atomicAdd(&cnt[at[n]], 1);
}
__global__ void prefix_kernel(const int* __restrict__ cnt, int* __restrict__ offs) {
    if (threadIdx.x == 0) { int s = 0; for (int i = 0; i < 64; i++) { offs[i] = s; s += cnt[i]; } offs[64] = s; }
}
__global__ void order_kernel(const int* __restrict__ at, const int* __restrict__ offs,
                             int* __restrict__ cur, int* __restrict__ order, int N) {
    int n = blockIdx.x*blockDim.x + threadIdx.x;
    if (n < N) { int t = at[n]; order[offs[t] + atomicAdd(&cur[t], 1)] = n; }
}

// ---------------------------------------------------------------------------
__device__ __forceinline__ void copy8(const float* __restrict__ in, bf16* __restrict__ out, float sgn) {
    float4 a = *(const float4*)in, b = *(const float4*)(in + 4);
    bf162 h[4] = { f2b2(sgn*a.x, sgn*a.y), f2b2(sgn*a.z, sgn*a.w),
                   f2b2(sgn*b.x, sgn*b.y), f2b2(sgn*b.z, sgn*b.w) };
    *(uint4*)out = *(uint4*)h;
}
__global__ void prep_all_kernel(const float* __restrict__ w0,
                                const float* __restrict__ w1r, const float* __restrict__ w1i,
                                const float* __restrict__ envw, const float* __restrict__ lpws,
                                const float* __restrict__ lpwv, const float* __restrict__ ohwss,
                                const float* __restrict__ ohwsg, const float* __restrict__ ohwvv,
                                const float* __restrict__ ohlws, const float* __restrict__ ohlwv,
                                const float* __restrict__ latents, bf16* __restrict__ bb,
                                size_t latN) {
    size_t g8 = ((size_t)blockIdx.x*blockDim.x + threadIdx.x)*8;
    if (g8 >= 2097152 + latN) return;
    if (g8 < 65536) {
        int i = (int)g8, k = i >> 9, c = i & 511;
        const float* s = (c < 256) ? w0 + (size_t)k*256 + c : w0 + (size_t)(256 + k)*256 + (c - 256);
        copy8(s, bb + WCPT + i, 1.f);
    } else if (g8 < 147456) {
        int i = (int)(g8 - 65536), k = i >> 8, c = i & 255;
        int src = (k < 128) ? k + 128 : k + 256;
        copy8(w0 + (size_t)src*256 + c, bb + W0MT + i, 1.f);
    } else if (g8 < 196608) {
        int i = (int)(g8 - 147456), r = i >> 7, c = i & 127;
        const float* s; float sgn = 1.f;
        if (r < 192) s = (c < 64) ? w1r + r*64 + c : w1i + r*64 + (c - 64);
        else { int r2 = r - 192; if (c < 64) { s = w1i + r2*64 + c; sgn = -1.f; } else s = w1r + r2*64 + (c - 64); }
        copy8(s, bb + W1CT + i, sgn);
    } else if (g8 < 221184) { int i = (int)(g8 - 196608); copy8(envw + i,  bb + ENVT  + i, 1.f);
    } else if (g8 < 237568) { int i = (int)(g8 - 221184); copy8(lpws + i,  bb + LPWST + i, 1.f);
    } else if (g8 < 241664) { int i = (int)(g8 - 237568); copy8(lpwv + i,  bb + LPWVT + i, 1.f);
    } else if (g8 < 1290240) {
        int i = (int)(g8 - 241664), ut = i >> 7, n = i & 127;
        copy8(ohwss + i, bb + WSC + (size_t)ut*192 + n, 1.f);
    } else if (g8 < 1814528) {
        int i = (int)(g8 - 1290240), ut = i >> 6, gg = i & 63;
        copy8(ohwsg + i, bb + WSC + (size_t)ut*192 + 128 + gg, 1.f);
    } else if (g8 < 2076672) { int i = (int)(g8 - 1814528); copy8(ohwvv + i, bb + WVVT + i, 1.f);
    } else if (g8 < 2093056) { int i = (int)(g8 - 2076672); copy8(ohlws + i, bb + OHLWT + i, 1.f);
    } else if (g8 < 2097152) { int i = (int)(g8 - 2093056); copy8(ohlwv + i, bb + OHLVT + i, 1.f);
    } else {
        size_t i = g8 - 2097152;
        if (i + 8 <= latN) copy8(latents + i, bb + LATB + i, 1.f);
        else for (size_t j = i; j < latN; j++) bb[LATB + j] = __float2bfloat16(latents[j]);
    }
}

// ---------------------------------------------------------------------------
__global__ void node_ln_kernel(const float* __restrict__ nf, const float* __restrict__ ws,
                               const float* __restrict__ bs, const float* __restrict__ wv,
                               bf16* __restrict__ ns, float* __restrict__ nv, int N) {
    int node = (blockIdx.x*blockDim.x + threadIdx.x) >> 5;
    int lane = threadIdx.x & 31;
    if (node >= N) return;
    const float* row = nf + (size_t)node*320;
    float s[4]; float sum = 0.f;
#pragma unroll
    for (int i = 0; i < 4; i++) { s[i] = row[lane + 32*i]; sum += s[i]; }
#pragma unroll
    for (int o = 16; o; o >>= 1) sum += __shfl_xor_sync(~0u, sum, o);
    float mu = sum*(1.f/128.f), var = 0.f;
#pragma unroll
    for (int i = 0; i < 4; i++) { s[i] -= mu; var += s[i]*s[i]; }
#pragma unroll
    for (int o = 16; o; o >>= 1) var += __shfl_xor_sync(~0u, var, o);
    float rs = rsqrtf(var*(1.f/128.f) + 1e-8f);
#pragma unroll
    for (int i = 0; i < 4; i++) {
        int c = lane + 32*i;
        ns[(size_t)node*128 + c] = __float2bfloat16(s[i]*rs*ws[c] + bs[c]);
    }
    float v[6]; float vs = 0.f;
#pragma unroll
    for (int i = 0; i < 6; i++) { v[i] = row[128 + lane + 32*i]; vs += v[i]*v[i]; }
#pragma unroll
    for (int o = 16; o; o >>= 1) vs += __shfl_xor_sync(~0u, vs, o);
    float rv = rsqrtf(vs*(1.f/192.f) + 1e-8f);
#pragma unroll
    for (int i = 0; i < 6; i++) { int c = lane + 32*i; nv[(size_t)node*192 + c] = v[i]*rv*wv[c/3]; }
}

__global__ void edge_prep_kernel(const float* __restrict__ ef, const int* __restrict__ ei,
                                 const int* __restrict__ act, const float* __restrict__ evec,
                                 const float* __restrict__ ws, const float* __restrict__ bs,
                                 const float* __restrict__ wv, const float* __restrict__ nv,
                                 bf16* __restrict__ esv0, bf16* __restrict__ vf12,
                                 float* __restrict__ Rout, int* __restrict__ idx, int E, int Etot) {
    __shared__ float evs[8][192];
    int wi = threadIdx.x >> 5, lane = threadIdx.x & 31;
    int e = blockIdx.x*8 + wi;
    if (e >= E) return;
    int ae = act[e];
    int ctr = ei[ae], nbr = ei[Etot + ae];
    if (lane == 0) { idx[e] = ctr; idx[E + e] = nbr; }
    const float* row = ef + (size_t)e*320;

    float s[4]; float sum = 0.f;
#pragma unroll
    for (int i = 0; i < 4; i++) { s[i] = row[lane + 32*i]; sum += s[i]; }
#pragma unroll
    for (int o = 16; o; o >>= 1) sum += __shfl_xor_sync(~0u, sum, o);
    float mu = sum*(1.f/128.f), var = 0.f;
#pragma unroll
    for (int i = 0; i < 4; i++) { s[i] -= mu; var += s[i]*s[i]; }
#pragma unroll
    for (int o = 16; o; o >>= 1) var += __shfl_xor_sync(~0u, var, o);
    float rs = rsqrtf(var*(1.f/128.f) + 1e-8f);
    bf16* esv = esv0 + (size_t)e*320;
#pragma unroll
    for (int i = 0; i < 4; i++) { int c = lane + 32*i; esv[c] = __float2bfloat16(s[i]*rs*ws[c] + bs[c]); }

    float v[6]; float vs = 0.f;
#pragma unroll
    for (int i = 0; i < 6; i++) { v[i] = row[128 + lane + 32*i]; vs += v[i]*v[i]; }
#pragma unroll
    for (int o = 16; o; o >>= 1) vs += __shfl_xor_sync(~0u, vs, o);
    float rv = rsqrtf(vs*(1.f/192.f) + 1e-8f);
#pragma unroll
    for (int i = 0; i < 6; i++) { int c = lane + 32*i; evs[wi][c] = v[i]*rv*wv[c/3]; }
    __syncwarp();

    float e0 = evec[(size_t)ae*3], e1 = evec[(size_t)ae*3+1], e2 = evec[(size_t)ae*3+2];
    float rn = rsqrtf(e0*e0 + e1*e1 + e2*e2 + 1e-8f);
    float ax = e0*rn, ay = e1*rn, az = e2*rn;
    float refx = (fabsf(ax) < 0.9f) ? 1.f : 0.f, refy = 1.f - refx;
    float bx = -az*refy, by = az*refx, bz = ax*refy - ay*refx;
    float rb = rsqrtf(bx*bx + by*by + bz*bz + 1e-8f);
    bx *= rb; by *= rb; bz *= rb;
    float cx = ay*bz - az*by, cy = az*bx - ax*bz, cz = ax*by - ay*bx;
    if (lane == 0) {
        float* Rp = Rout + (size_t)e*9;
        Rp[0]=ax; Rp[1]=ay; Rp[2]=az; Rp[3]=bx; Rp[4]=by; Rp[5]=bz; Rp[6]=cx; Rp[7]=cy; Rp[8]=cz;
    }
    bf16* vf = vf12 + (size_t)e*384;
#pragma unroll
    for (int i = 0; i < 6; i++) {
        int u = lane + 32*i;
        float vx, vy, vz;
        if (u < 64)       { const float* p = nv + (size_t)ctr*192 + u*3;        vx=p[0]; vy=p[1]; vz=p[2]; }
        else if (u < 128) { const float* p = &evs[wi][(u-64)*3];                vx=p[0]; vy=p[1]; vz=p[2]; }
        else              { const float* p = nv + (size_t)nbr*192 + (u-128)*3;  vx=p[0]; vy=p[1]; vz=p[2]; }
        esv[128 + u] = __float2bfloat16(ax*vx + ay*vy + az*vz);
        vf[u]        = __float2bfloat16(bx*vx + by*vy + bz*vz);
        vf[192 + u]  = __float2bfloat16(cx*vx + cy*vy + cz*vz);
    }
}

// ---------------------------------------------------------------------------
// bf16 GEMM (m16n8k16), BK=32 stages, A [M,K] ldmatrix, B [K,N] ldmatrix.trans.
// MODE 10: bf16 C = A@B*scale
// MODE 1:  main SO2; bn=0: fused silu->lps GEMM->env scatter; bn=128: gv
// MODE 4:  complex GEMM + rotation + fused lpv GEMM + env scatter (per plane)
// MODE 5:  merged typed gs/tg; MODE 7: typed gvm; MODE 8/9: final + residual
static constexpr int ASUB = 6144;
static constexpr int BSUB = 4352;
static constexpr int ASTG = 2*ASUB;           // 12288
static constexpr int BSTG = 2*BSUB;           // 8704
static constexpr int STG  = ASTG + BSTG;      // 20992
static constexpr int GEMM_SMEM  = 3*STG;      // 62976
static constexpr int GEMM_SMEM1 = 8*ASUB + 8*BSUB;  // 83968
// MODE4: plane staging 4*ASUB (24576) | lpwv 4*BSUB (17408) | Vs bf16 128x136 (34816)
static constexpr int M4_WOFF  = 4*ASUB;              // 24576
static constexpr int M4_VSOFF = M4_WOFF + 4*BSUB;    // 41984
static constexpr int GEMM_SMEM4 = M4_VSOFF + 128*136*2;  // 76800

template<int MODE, bool GATHER>
__global__ __launch_bounds__(256, 2)
void mma_gemm_kernel(const bf16* __restrict__ A, const bf16* __restrict__ B,
                     float* __restrict__ C, int M, int Nc, int K, int lda, int ldb,
                     float scale, const float* __restrict__ bias, const int* __restrict__ rowidx,
                     const int* __restrict__ ctr, const int* __restrict__ nbr,
                     const float* __restrict__ proj, const float* __restrict__ Rrot,
                     const float* __restrict__ gvbuf, const float* __restrict__ wenv,
                     float* __restrict__ agg, float* __restrict__ aux,
                     const float* __restrict__ nf, const float* __restrict__ resp,
                     const int* __restrict__ offs, const int* __restrict__ order,
                     int tOffB, size_t aplane, int Nnodes, int E,
                     const bf16* __restrict__ B2) {
    constexpr bool TYPED = (MODE == 5 || MODE == 7);
    extern __shared__ char smc[];
    const int tid = threadIdx.x, lane = tid & 31, wid = tid >> 5;
    const int g = lane >> 2, t = lane & 3;
    const int wm = (wid >> 2)*64, wn = (wid & 3)*32;

    int mplane = 0, bn;
    if (MODE == 7 || MODE == 9) { mplane = blockIdx.x; bn = 0; } else bn = blockIdx.x*128;
    const int bm = blockIdx.y*128;

    int Mloc = M, rowbase = 0, typ = 0;
    if (TYPED) {
        typ = blockIdx.z;
        rowbase = offs[typ];
        Mloc = offs[typ+1] - rowbase;
        if (Mloc == 0 || bm >= Mloc) return;
    }
    const bf16* Ause = A + (size_t)mplane*aplane;
    const bf16* Buse = B + (TYPED ? (size_t)typ*tOffB : 0);

    int arow = tid >> 1, ahalf = tid & 1;
    int r = bm + arow, gr;
    if (TYPED) { if (r >= Mloc) r = Mloc - 1; gr = order[rowbase + r]; }
    else       { if (r >= M) r = M - 1;       gr = GATHER ? rowidx[r] : r; }
    const bf16* asrc = Ause + (size_t)gr*lda + ahalf*8;
    int brow = tid >> 4, bc16 = tid & 15;
    int bcol = bn + bc16*8;
    int bby = (bcol < Nc) ? 16 : 0;
    if (bcol >= Nc) bcol = Nc - 8;
    const bf16* bsrc = Buse + (size_t)brow*ldb + bcol;

    uint32_t sbase = (uint32_t)__cvta_generic_to_shared(smc);
    uint32_t adst = sbase + arow*48 + ahalf*16;
    uint32_t bdst = sbase + ASTG + brow*272 + bc16*16;

    const int q = lane >> 3, rr8 = lane & 7;
    uint32_t aLd = sbase + ((wm + (q & 1)*8 + rr8)*24 + (q >> 1)*8)*2;
    uint32_t bLd = sbase + ASTG + ((q & 1)*8 + rr8)*272 + (wn + (q >> 1)*8)*2;

    const int kT = K >> 5;
    auto loadStage = [&](int slot, int k0) {
        uint32_t so = slot*STG;
        asm volatile("cp.async.cg.shared.global [%0], [%1], 16;"
                     :: "r"(adst + so), "l"(asrc + k0) : "memory");
        asm volatile("cp.async.cg.shared.global [%0], [%1], 16;"
                     :: "r"(adst + so + ASUB), "l"(asrc + k0 + 16) : "memory");
        asm volatile("cp.async.cg.shared.global [%0], [%1], 16, %2;"
                     :: "r"(bdst + so), "l"(bsrc + (size_t)k0*ldb), "r"(bby) : "memory");
        asm volatile("cp.async.cg.shared.global [%0], [%1], 16, %2;"
                     :: "r"(bdst + so + BSUB), "l"(bsrc + (size_t)(k0+16)*ldb), "r"(bby) : "memory");
        asm volatile("cp.async.commit_group;");
    };

    float acc[4][4][4];
#pragma unroll
    for (int mi = 0; mi < 4; mi++)
#pragma unroll
        for (int ni = 0; ni < 4; ni++)
#pragma unroll
            for (int j = 0; j < 4; j++) acc[mi][ni][j] = 0.f;

    loadStage(0, 0);
    if (kT > 1) loadStage(1, 32); else asm volatile("cp.async.commit_group;");

    for (int kt = 0; kt < kT; kt++) {
        asm volatile("cp.async.wait_group 1;");
        __syncthreads();
        int pf = kt + 2;
        if (pf < kT) loadStage(pf % 3, pf*32);
        else asm volatile("cp.async.commit_group;");

        uint32_t so = (kt % 3)*STG;
#pragma unroll
        for (int sub = 0; sub < 2; sub++) {
            uint32_t offA = so + sub*ASUB, offB = so + sub*BSUB;
            uint32_t af[4][4], bf[4][2];
#pragma unroll
            for (int mi = 0; mi < 4; mi++)
                asm volatile("ldmatrix.sync.aligned.m8n8.x4.shared.b16 {%0,%1,%2,%3}, [%4];"
                    : "=r"(af[mi][0]), "=r"(af[mi][1]), "=r"(af[mi][2]), "=r"(af[mi][3])
                    : "r"(aLd + offA + mi*16*48));
#pragma unroll
            for (int np = 0; np < 2; np++)
                asm volatile("ldmatrix.sync.aligned.m8n8.x4.trans.shared.b16 {%0,%1,%2,%3}, [%4];"
                    : "=r"(bf[2*np][0]), "=r"(bf[2*np][1]), "=r"(bf[2*np+1][0]), "=r"(bf[2*np+1][1])
                    : "r"(bLd + offB + np*32));
#pragma unroll
            for (int mi = 0; mi < 4; mi++)
#pragma unroll
                for (int ni = 0; ni < 4; ni++) {
                    asm volatile(
                        "mma.sync.aligned.m16n8k16.row.col.f32.bf16.bf16.f32 "
                        "{%0,%1,%2,%3}, {%4,%5,%6,%7}, {%8,%9}, {%0,%1,%2,%3};"
                        : "+f"(acc[mi][ni][0]), "+f"(acc[mi][ni][1]),
                          "+f"(acc[mi][ni][2]), "+f"(acc[mi][ni][3])
                        : "r"(af[mi][0]), "r"(af[mi][1]), "r"(af[mi][2]), "r"(af[mi][3]),
                          "r"(bf[ni][0]), "r"(bf[ni][1]));
                }
        }
    }

    // ---------------- epilogue ----------------
    const float INV = 0.28867513459481287f;

    if (MODE == 1 && bn == 0) {
        __syncthreads();
        uint32_t lpB = sbase + 8*ASUB;
#pragma unroll
        for (int it = 0; it < 8; it++) {
            int id = tid + 256*it;
            int k = id >> 4, c16 = id & 15;
            asm volatile("cp.async.cg.shared.global [%0], [%1], 16;"
                :: "r"(lpB + (k >> 4)*BSUB + (k & 15)*272 + c16*16),
                   "l"(B2 + (size_t)k*128 + c16*8) : "memory");
        }
        asm volatile("cp.async.commit_group;");
        const bf16* pcB = (const bf16*)proj;
#pragma unroll
        for (int mi = 0; mi < 4; mi++)
#pragma unroll
            for (int h = 0; h < 2; h++) {
                int rw = wm + mi*16 + g + 8*h;
                int row = bm + rw;
                const bf16* pc = pcB + (size_t)ctr[row]*512;
                const bf16* pn = pcB + (size_t)nbr[row]*512 + 256;
#pragma unroll
                for (int ni = 0; ni < 4; ni++) {
                    int c = wn + ni*8 + 2*t;
                    float2 pcv = __bfloat1622float2(*(const bf162*)&pc[c]);
                    float2 pnv = __bfloat1622float2(*(const bf162*)&pn[c]);
                    float v0 = (acc[mi][ni][2*h]   + pcv.x + pnv.x)*scale;
                    float v1 = (acc[mi][ni][2*h+1] + pcv.y + pnv.y)*scale;
                    bf162 m = f2b2(v0/(1.f+expf(-v0)), v1/(1.f+expf(-v1)));
                    *(bf162*)(smc + (size_t)(c >> 4)*ASUB + rw*48 + (c & 15)*2) = m;
                }
            }
        asm volatile("cp.async.wait_group 0;");
        __syncthreads();
#pragma unroll
        for (int mi = 0; mi < 4; mi++)
#pragma unroll
            for (int ni = 0; ni < 4; ni++)
#pragma unroll
                for (int j = 0; j < 4; j++) acc[mi][ni][j] = 0.f;
        uint32_t aLd2 = sbase + ((wm + (q & 1)*8 + rr8)*24 + (q >> 1)*8)*2;
        uint32_t bLd2 = sbase + 8*ASUB + ((q & 1)*8 + rr8)*272 + (wn + (q >> 1)*8)*2;
#pragma unroll
        for (int ks = 0; ks < 8; ks++) {
            uint32_t af[4][4], bf[4][2];
#pragma unroll
            for (int mi = 0; mi < 4; mi++)
                asm volatile("ldmatrix.sync.aligned.m8n8.x4.shared.b16 {%0,%1,%2,%3}, [%4];"
                    : "=r"(af[mi][0]), "=r"(af[mi][1]), "=r"(af[mi][2]), "=r"(af[mi][3])
                    : "r"(aLd2 + ks*ASUB + mi*16*48));
#pragma unroll
            for (int np = 0; np < 2; np++)
                asm volatile("ldmatrix.sync.aligned.m8n8.x4.trans.shared.b16 {%0,%1,%2,%3}, [%4];"
                    : "=r"(bf[2*np][0]), "=r"(bf[2*np][1]), "=r"(bf[2*np+1][0]), "=r"(bf[2*np+1][1])
                    : "r"(bLd2 + ks*BSUB + np*32));
#pragma unroll
            for (int mi = 0; mi < 4; mi++)
#pragma unroll
                for (int ni = 0; ni < 4; ni++) {
                    asm volatile(
                        "mma.sync.aligned.m16n8k16.row.col.f32.bf16.bf16.f32 "
                        "{%0,%1,%2,%3}, {%4,%5,%6,%7}, {%8,%9}, {%0,%1,%2,%3};"
                        : "+f"(acc[mi][ni][0]), "+f"(acc[mi][ni][1]),
                          "+f"(acc[mi][ni][2]), "+f"(acc[mi][ni][3])
                        : "r"(af[mi][0]), "r"(af[mi][1]), "r"(af[mi][2]), "r"(af[mi][3]),
                          "r"(bf[ni][0]), "r"(bf[ni][1]));
                }
        }
        const float isq128 = 0.08838834764831845f;
#pragma unroll
        for (int mi = 0; mi < 4; mi++)
#pragma unroll
            for (int h = 0; h < 2; h++) {
                int row = bm + wm + mi*16 + g + 8*h;
                float* ap = agg + (size_t)ctr[row]*128;
                const bf16* we = (const bf16*)wenv + (size_t)row*192;
#pragma unroll
                for (int ni = 0; ni < 4; ni++) {
                    int c = wn + ni*8 + 2*t;
                    float2 w = __bfloat1622float2(*(const bf162*)&we[c]);
                    atomicAdd(&ap[c],   (acc[mi][ni][2*h]  *isq128 + bias[c])  *w.x*INV);
                    atomicAdd(&ap[c+1], (acc[mi][ni][2*h+1]*isq128 + bias[c+1])*w.y*INV);
                }
            }
        return;
    }

    if (MODE == 4) {
        // Fused: stage vp/vm (bf16) -> per-plane rotation -> lpv GEMM -> env scatter
        __syncthreads();
        {   // load lpwv 64x64 (512 x 16B chunks), 2 chunks per thread
#pragma unroll
            for (int it = 0; it < 2; it++) {
                int id = tid + 256*it;        // 0..511
                int k = id >> 3, c16 = id & 7;
                asm volatile("cp.async.cg.shared.global [%0], [%1], 16;"
                    :: "r"(sbase + M4_WOFF + (k >> 4)*BSUB + (k & 15)*272 + c16*16),
                       "l"(B2 + (size_t)k*64 + c16*8) : "memory");
            }
            asm volatile("cp.async.commit_group;");
        }
        bf16* Vs = (bf16*)(smc + M4_VSOFF);
#pragma unroll
        for (int mi = 0; mi < 4; mi++)
#pragma unroll
            for (int h = 0; h < 2; h++) {
                int rw = wm + mi*16 + g + 8*h;
#pragma unroll
                for (int ni = 0; ni < 4; ni++) {
                    int c = wn + ni*8 + 2*t;
                    *(bf162*)&Vs[rw*136 + c] = f2b2(acc[mi][ni][2*h]*scale, acc[mi][ni][2*h+1]*scale);
                }
            }
        asm volatile("cp.async.wait_group 0;");
        const int wm2 = (wid >> 1)*32, wn2 = (wid & 1)*32;
        uint32_t aBase2 = sbase + (wm2 + (q & 1)*8 + rr8)*48 + (q >> 1)*16;
        uint32_t bBase2 = sbase + M4_WOFF + ((q & 1)*8 + rr8)*272 + (wn2 + (q >> 1)*8)*2;
        const bf16* gvB = (const bf16*)gvbuf;

        for (int m = 0; m < 3; m++) {
            __syncthreads();   // previous GEMM reads done (and Vs/lpwv ready on m=0)
            for (int rw = wid; rw < 128; rw += 8) {
                int e = bm + rw;
                const float* Rp = Rrot + (size_t)e*9;
                float Rm0 = Rp[m], Rm1 = Rp[3+m], Rm2 = Rp[6+m];
                const bf16* gvp = gvB + (size_t)e*128;
#pragma unroll
                for (int i = 0; i < 2; i++) {
                    int u = lane + 32*i;
                    float sg = __bfloat162float(gvp[u]);
                    float i0 = __bfloat162float(gvp[64 + u]);
                    float i1 = __bfloat162float(Vs[rw*136 + u]);
                    float i2 = __bfloat162float(Vs[rw*136 + 64 + u]);
                    *(bf16*)(smc + (size_t)(u >> 4)*ASUB + rw*48 + (u & 15)*2) =
                        __float2bfloat16(sg*(Rm0*i0 + Rm1*i1 + Rm2*i2));
                }
            }
            __syncthreads();
            float acc2[2][4][4];
#pragma unroll
            for (int mi = 0; mi < 2; mi++)
#pragma unroll
                for (int ni = 0; ni < 4; ni++)
#pragma unroll
                    for (int j = 0; j < 4; j++) acc2[mi][ni][j] = 0.f;
#pragma unroll
            for (int ks = 0; ks < 4; ks++) {
                uint32_t af2[2][4], bf2[4][2];
#pragma unroll
                for (int mi = 0; mi < 2; mi++)
                    asm volatile("ldmatrix.sync.aligned.m8n8.x4.shared.b16 {%0,%1,%2,%3}, [%4];"
                        : "=r"(af2[mi][0]), "=r"(af2[mi][1]), "=r"(af2[mi][2]), "=r"(af2[mi][3])
                        : "r"(aBase2 + ks*ASUB + mi*16*48));
#pragma unroll
                for (int np = 0; np < 2; np++)
                    asm volatile("ldmatrix.sync.aligned.m8n8.x4.trans.shared.b16 {%0,%1,%2,%3}, [%4];"
                        : "=r"(bf2[2*np][0]), "=r"(bf2[2*np][1]), "=r"(bf2[2*np+1][0]), "=r"(bf2[2*np+1][1])
                        : "r"(bBase2 + ks*BSUB + np*32));
#pragma unroll
                for (int mi = 0; mi < 2; mi++)
#pragma unroll
                    for (int ni = 0; ni < 4; ni++) {
                        asm volatile(
                            "mma.sync.aligned.m16n8k16.row.col.f32.bf16.bf16.f32 "
                            "{%0,%1,%2,%3}, {%4,%5,%6,%7}, {%8,%9}, {%0,%1,%2,%3};"
                            : "+f"(acc2[mi][ni][0]), "+f"(acc2[mi][ni][1]),
                              "+f"(acc2[mi][ni][2]), "+f"(acc2[mi][ni][3])
                            : "r"(af2[mi][0]), "r"(af2[mi][1]), "r"(af2[mi][2]), "r"(af2[mi][3]),
                              "r"(bf2[ni][0]), "r"(bf2[ni][1]));
                    }
            }
#pragma unroll
            for (int mi = 0; mi < 2; mi++)
#pragma unroll
                for (int h = 0; h < 2; h++) {
                    int row = bm + wm2 + mi*16 + g + 8*h;
                    float* ap = agg + (size_t)m*Nnodes*64 + (size_t)ctr[row]*64;
                    const bf16* we = (const bf16*)wenv + (size_t)row*192 + 128;
#pragma unroll
                    for (int ni = 0; ni < 4; ni++) {
                        int c = wn2 + ni*8 + 2*t;
                        float2 w = __bfloat1622float2(*(const bf162*)&we[c]);
                        atomicAdd(&ap[c],   acc2[mi][ni][2*h]  *0.125f*w.x*INV);
                        atomicAdd(&ap[c+1], acc2[mi][ni][2*h+1]*0.125f*w.y*INV);
                    }
                }
        }
        return;
    }

    float alpha = 0.f, beta = 0.f;
    if (MODE == 8 || MODE == 9) { alpha = 1.f/(1.f + expf(-resp[0])); beta = 1.f - alpha; }

#pragma unroll
    for (int mi = 0; mi < 4; mi++) {
        int r0 = bm + wm + mi*16 + g;
#pragma unroll
        for (int h = 0; h < 2; h++) {
            int row = r0 + 8*h;
            if (row >= (TYPED ? Mloc : M)) continue;
            if (MODE == 10) {
                bf16* Cb = (bf16*)C;
#pragma unroll
                for (int ni = 0; ni < 4; ni++) {
                    int c = bn + wn + ni*8 + 2*t;
                    if (c >= Nc) continue;
                    *(bf162*)&Cb[(size_t)row*Nc + c] =
                        f2b2(acc[mi][ni][2*h]*scale, acc[mi][ni][2*h+1]*scale);
                }
            } else if (MODE == 1) {   // bn == 128: gate/vraw -> gv
                const bf16* pc = (const bf16*)proj + (size_t)ctr[row]*512;
                const bf16* pn = (const bf16*)proj + (size_t)nbr[row]*512 + 256;
                bf16* auxB = (bf16*)aux;
#pragma unroll
                for (int ni = 0; ni < 4; ni++) {
                    int c = bn + wn + ni*8 + 2*t;
                    float2 pcv = __bfloat1622float2(*(const bf162*)&pc[c]);
                    float2 pnv = __bfloat1622float2(*(const bf162*)&pn[c]);
                    float v0 = (acc[mi][ni][2*h]   + pcv.x + pnv.x)*scale;
                    float v1 = (acc[mi][ni][2*h+1] + pcv.y + pnv.y)*scale;
                    if (c < 192) {
                        *(bf162*)&auxB[(size_t)row*128 + c-128] =
                            f2b2(1.f/(1.f+expf(-v0)), 1.f/(1.f+expf(-v1)));
                    } else {
                        *(bf162*)&auxB[(size_t)row*128 + c-128] = f2b2(v0, v1);
                    }
                }
            } else if (MODE == 5) {
                int node = order[rowbase + row];
                bf16* Cb = (bf16*)C;
#pragma unroll
                for (int ni = 0; ni < 4; ni++) {
                    int c = bn + wn + ni*8 + 2*t;
                    float v0 = acc[mi][ni][2*h]*scale, v1 = acc[mi][ni][2*h+1]*scale;
                    if (c < 128) {
                        *(bf162*)&Cb[(size_t)node*128 + c] = f2b2(v0/(1.f+expf(-v0)), v1/(1.f+expf(-v1)));
                    } else if (c < 192) {
                        *(float2*)&aux[(size_t)node*64 + c-128] =
                            make_float2(1.f/(1.f+expf(-v0)), 1.f/(1.f+expf(-v1)));
                    }
                }
            } else if (MODE == 7) {
                int node = order[rowbase + row];
                const float* tgp = gvbuf + (size_t)node*64;
                bf16* Cb = (bf16*)C;
#pragma unroll
                for (int ni = 0; ni < 4; ni++) {
                    int c = wn + ni*8 + 2*t;
                    if (c >= Nc) continue;
                    *(bf162*)&Cb[(size_t)mplane*aplane + (size_t)node*64 + c] =
                        f2b2(acc[mi][ni][2*h]*scale*tgp[c], acc[mi][ni][2*h+1]*scale*tgp[c+1]);
                }
            } else if (MODE == 8) {
#pragma unroll
                for (int ni = 0; ni < 4; ni++) {
                    int c = wn + ni*8 + 2*t;
                    float a0 = acc[mi][ni][2*h]*scale + bias[c];
                    float a1 = acc[mi][ni][2*h+1]*scale + bias[c+1];
                    *(float2*)&C[(size_t)row*320 + c] =
                        make_float2(alpha*nf[(size_t)row*320 + c] + beta*a0,
                                    alpha*nf[(size_t)row*320 + c + 1] + beta*a1);
                }
            } else if (MODE == 9) {
#pragma unroll
                for (int ni = 0; ni < 4; ni++) {
                    int c = wn + ni*8 + 2*t;
                    if (c >= Nc) continue;
                    size_t o0 = (size_t)row*320 + 128 + 3*c + mplane;
                    size_t o1 = (size_t)row*320 + 128 + 3*(c+1) + mplane;
                    C[o0] = alpha*nf[o0] + beta*acc[mi][ni][2*h]*scale;
                    C[o1] = alpha*nf[o1] + beta*acc[mi][ni][2*h+1]*scale;
                }
            }
        }
    }
}

// ---------------------------------------------------------------------------
extern "C" void kernel_launch(void* const* d_in, const int* in_sizes, int n_in,
                              void* d_out, int out_size) {
    const float* latents = (const float*)d_in[0];
    const float* nf    = (const float*)d_in[1];
    const float* ef    = (const float*)d_in[2];
    const int*   at    = (const int*)  d_in[3];
    const int*   ei    = (const int*)  d_in[5];
    const float* evec  = (const float*)d_in[6];
    const int*   act   = (const int*)  d_in[7];
    const float* snws  = (const float*)d_in[8];
    const float* snbs  = (const float*)d_in[9];
    const float* snwv  = (const float*)d_in[10];
    const float* sews  = (const float*)d_in[11];
    const float* sebs  = (const float*)d_in[12];
    const float* sewv  = (const float*)d_in[13];
    const float* so2w0 = (const float*)d_in[14];
    const float* w1r   = (const float*)d_in[15];
    const float* w1i   = (const float*)d_in[16];
    const float* envw  = (const float*)d_in[17];
    const float* lpws  = (const float*)d_in[18];
    const float* lpbs  = (const float*)d_in[19];
    const float* lpwv  = (const float*)d_in[20];
    const float* ohwss = (const float*)d_in[21];
    const float* ohwsg = (const float*)d_in[22];
    const float* ohwvv = (const float*)d_in[23];
    const float* ohlws = (const float*)d_in[24];
    const float* ohlbs = (const float*)d_in[25];
    const float* ohlwv = (const float*)d_in[26];
    const float* resp  = (const float*)d_in[27];

    int N = in_sizes[1]/320, E = in_sizes[7], Etot = in_sizes[5]/2;
    size_t latN = (size_t)in_sizes[0];

    float* fb = nullptr;  cudaGetSymbolAddress((void**)&fb, g_buf);
    bf16* bb = nullptr;   cudaGetSymbolAddress((void**)&bb, g_bbuf);
    int* idx = nullptr;   cudaGetSymbolAddress((void**)&idx, g_idx);
    int* cnt = nullptr;   cudaGetSymbolAddress((void**)&cnt, g_cnt);
    int* offs = nullptr;  cudaGetSymbolAddress((void**)&offs, g_offs);
    int* order = nullptr; cudaGetSymbolAddress((void**)&order, g_order);

    float *nv = fb+NV_OFF, *Rbuf = fb+R_OFF, *aggs = fb+AGGS_OFF, *aggv = fb+AGGV_OFF, *tgb = fb+TG_OFF;
    bf16 *nsB = bb+NSB, *esvB = bb+ESVB, *vfB = bb+VF12B,
         *latB = bb+LATB, *gsB = bb+GSB, *gvmB = bb+GVMB, *agsB = bb+AGSB, *agvB = bb+AGVB,
         *projB = bb+PROJB, *gvB = bb+GVB, *wenvB = bb+WENVB,
         *wcpK = bb+WCPT, *w0mK = bb+W0MT, *w1cK = bb+W1CT, *envK = bb+ENVT, *lpwsK = bb+LPWST,
         *lpwvK = bb+LPWVT, *wscK = bb+WSC, *wvvK = bb+WVVT, *ohlwK = bb+OHLWT, *ohlvK = bb+OHLVT;
    int *ctr = idx, *nbr = idx + E;

    const float isq576 = 0.041666666666666664f, isq192 = 0.07216878364870323f,
                isq128 = 0.08838834764831845f, n_ss = 0.011048543456039806f, n_vv = 0.015625f;

    cudaFuncSetAttribute(mma_gemm_kernel<10,false>, cudaFuncAttributeMaxDynamicSharedMemorySize, GEMM_SMEM);
    cudaFuncSetAttribute(mma_gemm_kernel<10,true>,  cudaFuncAttributeMaxDynamicSharedMemorySize, GEMM_SMEM);
    cudaFuncSetAttribute(mma_gemm_kernel<1,false>, cudaFuncAttributeMaxDynamicSharedMemorySize, GEMM_SMEM1);
    cudaFuncSetAttribute(mma_gemm_kernel<4,false>, cudaFuncAttributeMaxDynamicSharedMemorySize, GEMM_SMEM4);
    cudaFuncSetAttribute(mma_gemm_kernel<5,false>, cudaFuncAttributeMaxDynamicSharedMemorySize, GEMM_SMEM);
    cudaFuncSetAttribute(mma_gemm_kernel<7,false>, cudaFuncAttributeMaxDynamicSharedMemorySize, GEMM_SMEM);
    cudaFuncSetAttribute(mma_gemm_kernel<8,false>, cudaFuncAttributeMaxDynamicSharedMemorySize, GEMM_SMEM);
    cudaFuncSetAttribute(mma_gemm_kernel<9,false>, cudaFuncAttributeMaxDynamicSharedMemorySize, GEMM_SMEM);

    int etile = (E + 127)/128, ntile = (N + 127)/128;

    zero_kernel<<<(int)(((size_t)N*320 + 255)/256), 256>>>(aggs, (size_t)N*320);
    zero_kernel<<<1, 128>>>((float*)cnt, 128);
    node_ln_kernel<<<(N + 7)/8, 256>>>(nf, snws, snbs, snwv, nsB, nv, N);
    {
        size_t tot8 = (2097152 + latN + 7)/8;
        prep_all_kernel<<<(int)((tot8 + 255)/256), 256>>>(
            so2w0, w1r, w1i, envw, lpws, lpwv, ohwss, ohwsg, ohwvv, ohlws, ohlwv,
            latents, bb, latN);
    }
    count_kernel<<<(N + 255)/256, 256>>>(at, cnt, N);
    prefix_kernel<<<1, 32>>>(cnt, offs);
    order_kernel<<<(N + 255)/256, 256>>>(at, offs, cnt + 64, order, N);
    edge_prep_kernel<<<(E + 7)/8, 256>>>(ef, ei, act, evec, sews, sebs, sewv,
                                         nv, esvB, vfB, Rbuf, idx, E, Etot);

    // proj = ns @ wcp  (N x 512, bf16 out)
    mma_gemm_kernel<10,false><<<dim3(4, ntile), 256, GEMM_SMEM>>>(
        nsB, wcpK, (float*)projB, N, 512, 128, 128, 512, 1.0f, nullptr, nullptr,
        nullptr, nullptr, nullptr, nullptr, nullptr, nullptr, nullptr, nullptr,
        nullptr, nullptr, nullptr, nullptr, 0, 0, N, E, nullptr);
    // wenv = latB[act] @ env / sqrt(128)  (bf16 out)
    mma_gemm_kernel<10,true><<<dim3(2, etile), 256, GEMM_SMEM>>>(
        latB, envK, (float*)wenvB, E, 192, 128, 128, 192, isq128, nullptr, act,
        nullptr, nullptr, nullptr, nullptr, nullptr, nullptr, nullptr, nullptr,
        nullptr, nullptr, nullptr, nullptr, 0, 0, N, E, nullptr);
    // main SO2; bn=0: fused silu+lps GEMM+scatter; bn=128: gv
    mma_gemm_kernel<1,false><<<dim3(2, etile), 256, GEMM_SMEM1>>>(
        esvB, w0mK, nullptr, E, 256, 320, 320, 256, isq576, lpbs, nullptr,
        ctr, nbr, (const float*)projB, nullptr, nullptr, (const float*)wenvB, aggs, (float*)gvB,
        nullptr, nullptr, nullptr, nullptr, 0, 0, N, E, lpwsK);
    // complex GEMM + rotation + fused lpv GEMM + scatter -> aggv
    mma_gemm_kernel<4,false><<<dim3(1, etile), 256, GEMM_SMEM4>>>(
        vfB, w1cK, nullptr, E, 128, 384, 384, 128, isq192, nullptr, nullptr,
        ctr, nullptr, nullptr, Rbuf, (const float*)gvB, (const float*)wenvB, aggv, nullptr,
        nullptr, nullptr, nullptr, nullptr, 0, 0, N, E, lpwvK);
    // aggs|aggv -> bf16
    c2b_kernel<<<(int)(((size_t)N*320 + 255)/256), 256>>>(aggs, agsB, (size_t)N*320);
    // merged typed gs/tg: Nc=192 against wsc
    mma_gemm_kernel<5,false><<<dim3(2, 2, 64), 256, GEMM_SMEM>>>(
        agsB, wscK, (float*)gsB, N, 192, 128, 128, 64*192, n_ss, nullptr, nullptr,
        nullptr, nullptr, nullptr, nullptr, nullptr, nullptr, nullptr, tgb,
        nullptr, nullptr, offs, order, 192, 0, N, E, nullptr);
    // typed, 3 planes: gvm = bf16(tg * (aggvB @ wvv[:,t,:] * n_vv))
    mma_gemm_kernel<7,false><<<dim3(3, 2, 64), 256, GEMM_SMEM>>>(
        agvB, wvvK, (float*)gvmB, N, 64, 64, 64, 64*64, n_vv, nullptr, nullptr,
        nullptr, nullptr, nullptr, nullptr, tgb, nullptr, nullptr, nullptr,
        nullptr, nullptr, offs, order, 64, (size_t)N*64, N, E, nullptr);
    // final scalar: out[:,0:128]
    mma_gemm_kernel<8,false><<<dim3(1, ntile), 256, GEMM_SMEM>>>(
        gsB, ohlwK, (float*)d_out, N, 128, 128, 128, 128, isq128, ohlbs, nullptr,
        nullptr, nullptr, nullptr, nullptr, nullptr, nullptr, nullptr, nullptr,
        nf, resp, nullptr, nullptr, 0, 0, N, E, nullptr);
    // final vector: out[:,128+3k+m]
    mma_gemm_kernel<9,false><<<dim3(3, ntile), 256, GEMM_SMEM>>>(
        gvmB, ohlvK, (float*)d_out, N, 64, 64, 64, 64, 0.125f, nullptr, nullptr,
        nullptr, nullptr, nullptr, nullptr, nullptr, nullptr, nullptr, nullptr,
        nf, resp, nullptr, nullptr, 0, (size_t)N*64, N, E, nullptr);
}